// round 16
// baseline (speedup 1.0000x reference)
#include <cuda_runtime.h>
#include <math_constants.h>
#include <cstdint>

// ChamferDistance: x1,x2 = [B=8, N=M=8192, 3] fp32.
// out = [ loss (1) | dist1 (B*N) | dist2 (B*M) ]
//
// R16: x-binned pruned NN, queue-balanced, double-buffered.
//  prep: zero(+queue reset)/hist/prefix/scatter -> bin-grouped float4{x,y,z,idx}.
//  nn:  persistent 444 CTAs x 256 thr (3/SM); dynamic queue over 512 chunks
//       (256 bin-ordered A each). Per chunk: seed-scan B positions covering
//       [amin,amax]; CTA-max bound R; residual scans [amin-R,amax+R] minus
//       seed. Scans use the R6 engine: packed-dup smem tiles, double-buffered,
//       ONE barrier per 256-cand round. Exact NN (superset argument) =>
//       bit-deterministic despite nondeterministic scatter order & pop order.
//  Plain per-A stores (disjoint ownership). 2-stage loss reduction.

constexpr int Bc = 8;
constexpr int Nc = 8192;
constexpr int NBINS = 256;
constexpr float XLO = -4.5f;
constexpr float INV_H = NBINS / 9.0f;
constexpr int NCB = 16;                        // cloud(2) * batch(8)
constexpr int NN_THREADS = 256;
constexpr int CHUNK_A = 256;                   // A-points per chunk (PTS=1)
constexpr int CHUNKS_PER_CB = Nc / CHUNK_A;    // 32
constexpr int NCHUNKS = NCB * CHUNKS_PER_CB;   // 512
constexpr int NN_GRID = 444;                   // 3 CTAs per SM, persistent
constexpr int RB = 256;                        // candidates per round
constexpr int JP = RB / 2;                     // 128 j-pairs per tile

__device__ float4 g_scat[NCB][Nc];
__device__ int g_cnt[NCB][NBINS];
__device__ int g_start[NCB][NBINS + 1];
__device__ int g_cur[NCB][NBINS];
__device__ int g_qhead;
__device__ float g_partials[128];

__device__ __forceinline__ unsigned long long pk2(float lo, float hi) {
    unsigned long long r;
    asm("mov.b64 %0, {%1, %2};" : "=l"(r) : "f"(lo), "f"(hi));
    return r;
}
__device__ __forceinline__ unsigned long long ffma2(unsigned long long a,
                                                    unsigned long long b,
                                                    unsigned long long c) {
    unsigned long long d;
    asm("fma.rn.f32x2 %0, %1, %2, %3;" : "=l"(d) : "l"(a), "l"(b), "l"(c));
    return d;
}
__device__ __forceinline__ void upk2(unsigned long long v, float& lo, float& hi) {
    asm("mov.b64 {%0, %1}, %2;" : "=f"(lo), "=f"(hi) : "l"(v));
}

__device__ __forceinline__ int bin_of(float x) {
    float v = (x - XLO) * INV_H;
    v = fminf(fmaxf(v, 0.0f), 255.0f);         // +-inf safe
    return (int)v;
}

// ---------------- binning kernels ----------------

__global__ void __launch_bounds__(512) zero_kernel() {
    int* p = &g_cnt[0][0];
#pragma unroll
    for (int k = 0; k < 8; k++) p[k * 512 + threadIdx.x] = 0;
    if (threadIdx.x == 0) g_qhead = 0;
}

__global__ void __launch_bounds__(512)
hist_kernel(const float* __restrict__ x1, const float* __restrict__ x2) {
    const int gid = blockIdx.x * 512 + threadIdx.x;
    const int c = gid >> 16;
    const int r = gid & 65535;
    const int b = r >> 13;
    const int i = r & 8191;
    const float* src = c ? x2 : x1;
    const float x = src[((size_t)b * Nc + i) * 3];
    atomicAdd(&g_cnt[c * 8 + b][bin_of(x)], 1);
}

__global__ void __launch_bounds__(512) prefix_kernel() {
    const int cb = threadIdx.x >> 5;
    const int lane = threadIdx.x & 31;
    int cnt[8];
    int s = 0;
#pragma unroll
    for (int k = 0; k < 8; k++) { cnt[k] = g_cnt[cb][lane * 8 + k]; s += cnt[k]; }
    int run = s;
#pragma unroll
    for (int d = 1; d < 32; d <<= 1) {
        int v = __shfl_up_sync(0xffffffffu, run, d);
        if (lane >= d) run += v;
    }
    int excl = run - s;
#pragma unroll
    for (int k = 0; k < 8; k++) {
        g_start[cb][lane * 8 + k] = excl;
        g_cur[cb][lane * 8 + k] = excl;
        excl += cnt[k];
    }
    if (lane == 31) g_start[cb][NBINS] = excl;
}

__global__ void __launch_bounds__(512)
scatter_kernel(const float* __restrict__ x1, const float* __restrict__ x2) {
    const int gid = blockIdx.x * 512 + threadIdx.x;
    const int c = gid >> 16;
    const int r = gid & 65535;
    const int b = r >> 13;
    const int i = r & 8191;
    const float* src = c ? x2 : x1;
    const float* p = src + ((size_t)b * Nc + i) * 3;
    const float x = p[0], y = p[1], z = p[2];
    const int cb = c * 8 + b;
    const int pos = atomicAdd(&g_cur[cb][bin_of(x)], 1);
    g_scat[cb][pos] = make_float4(x, y, z, __int_as_float(i));
}

// ---------------- NN kernel (persistent, queue-balanced) ----------------

__global__ void __launch_bounds__(NN_THREADS, 3)
nn_kernel(float* __restrict__ dist1, float* __restrict__ dist2)
{
    __shared__ __align__(16) float tile[2][JP * 8];    // 2 x 4 KB
    __shared__ float sred[NN_THREADS];
    __shared__ int s_chunk;

    const int tid = threadIdx.x;

    for (;;) {
        if (tid == 0) s_chunk = atomicAdd(&g_qhead, 1);
        __syncthreads();
        const int c = s_chunk;
        __syncthreads();                   // s_chunk consumed before next write
        if (c >= NCHUNKS) break;

        const int cbA = c >> 5;            // [0,16)
        const int seg = c & 31;
        const int cbB = cbA ^ 8;
        const int dir = cbA >> 3;
        const int b = cbA & 7;
        const float4* __restrict__ scatB = g_scat[cbB];
        const int* __restrict__ gs = g_start[cbB];

        // this thread's single A point
        const float4 A = g_scat[cbA][seg * CHUNK_A + tid];
        const float ax = A.x;
        const unsigned long long axp = pk2(A.x, A.x);
        const unsigned long long ayp = pk2(A.y, A.y);
        const unsigned long long azp = pk2(A.z, A.z);
        const float n1 = fmaf(A.x, A.x, fmaf(A.y, A.y, A.z * A.z));
        const int oi = __float_as_int(A.w);
        float eminE = CUDART_INF_F, eminO = CUDART_INF_F;

        // chunk x-range
        sred[tid] = ax;
        __syncthreads();
        for (int w = NN_THREADS / 2; w > 0; w >>= 1) {
            if (tid < w) sred[tid] = fminf(sred[tid], sred[tid + w]);
            __syncthreads();
        }
        const float amin = sred[0];
        __syncthreads();
        sred[tid] = ax;
        __syncthreads();
        for (int w = NN_THREADS / 2; w > 0; w >>= 1) {
            if (tid < w) sred[tid] = fmaxf(sred[tid], sred[tid + w]);
            __syncthreads();
        }
        const float amax = sred[0];
        __syncthreads();

        // double-buffered range scan (R6 engine, one barrier per round)
        auto fill = [&](int base, int hi, int buf) {
            if (tid < JP) {
                const int i0 = base + 2 * tid;
                float4 q0 = make_float4(0.f, 0.f, 0.f, 0.f);
                float4 q1 = make_float4(0.f, 0.f, 0.f, 0.f);
                float n2e = 1e30f, n2o = 1e30f;
                if (i0 < hi) {
                    q0 = scatB[i0];
                    n2e = fmaf(q0.x, q0.x, fmaf(q0.y, q0.y, q0.z * q0.z));
                }
                if (i0 + 1 < hi) {
                    q1 = scatB[i0 + 1];
                    n2o = fmaf(q1.x, q1.x, fmaf(q1.y, q1.y, q1.z * q1.z));
                }
                float4* sm = reinterpret_cast<float4*>(&tile[buf][tid * 8]);
                sm[0] = make_float4(-2.f * q0.x, -2.f * q1.x, -2.f * q0.y, -2.f * q1.y);
                sm[1] = make_float4(-2.f * q0.z, -2.f * q1.z, n2e, n2o);
            }
        };
        auto scan_range = [&](int lo, int hi) {
            if (lo >= hi) return;
            const int nr = (hi - lo + RB - 1) >> 8;
            fill(lo, hi, 0);
            for (int r = 0; r < nr; r++) {
                const int buf = r & 1;
                __syncthreads();           // fill(r) visible; compute(r-1) done
                if (r + 1 < nr) fill(lo + (r + 1) * RB, hi, buf ^ 1);
                const ulonglong2* sp = reinterpret_cast<const ulonglong2*>(tile[buf]);
#pragma unroll 8
                for (int jj = 0; jj < JP; jj++) {
                    const ulonglong2 c0 = sp[2 * jj];
                    const ulonglong2 c1 = sp[2 * jj + 1];
                    unsigned long long e = ffma2(axp, c0.x, c1.y);
                    e = ffma2(ayp, c0.y, e);
                    e = ffma2(azp, c1.x, e);
                    float flo, fhi;
                    upk2(e, flo, fhi);
                    eminE = fminf(eminE, flo);
                    eminO = fminf(eminO, fhi);
                }
            }
            __syncthreads();               // compute done before next fill
        };

        // seed: positions covering [amin, amax]
        const int slo = gs[bin_of(amin)];
        const int shi = gs[bin_of(amax) + 1];
        scan_range(slo, shi);

        // bound R from chunk-max best-so-far (u=INF if seed empty -> full scan)
        float u = n1 + fminf(eminE, eminO);
        sred[tid] = u;
        __syncthreads();
        for (int w = NN_THREADS / 2; w > 0; w >>= 1) {
            if (tid < w) sred[tid] = fmaxf(sred[tid], sred[tid + w]);
            __syncthreads();
        }
        const float R = sqrtf(fmaxf(sred[0], 0.0f)) * 1.0005f + 1e-3f;
        __syncthreads();

        // residual: [flo, slo) and [shi, fhi)
        const int flo = gs[bin_of(amin - R)];
        const int fhi = gs[bin_of(amax + R) + 1];
        scan_range(flo, slo);
        scan_range(shi, fhi);

        // store (each A owned by exactly one chunk, popped exactly once)
        float* __restrict__ outd = dir ? dist2 : dist1;
        outd[(size_t)b * Nc + oi] = fmaxf(n1 + fminf(eminE, eminO), 0.0f);
    }
}

// ---------------- deterministic 2-stage loss reduction ----------------

__global__ void __launch_bounds__(256)
sum_stage1(const float* __restrict__ dists)
{
    __shared__ float red[256];
    const int tid = threadIdx.x;
    const int base = blockIdx.x * 1024;
    float s = 0.0f;
#pragma unroll
    for (int i = 0; i < 4; i++) s += dists[base + i * 256 + tid];
    red[tid] = s;
    __syncthreads();
    for (int w = 128; w > 0; w >>= 1) {
        if (tid < w) red[tid] += red[tid + w];
        __syncthreads();
    }
    if (tid == 0) g_partials[blockIdx.x] = red[0];
}

__global__ void __launch_bounds__(128)
sum_stage2(float* __restrict__ out)
{
    __shared__ float red[128];
    const int tid = threadIdx.x;
    red[tid] = g_partials[tid];
    __syncthreads();
    for (int w = 64; w > 0; w >>= 1) {
        if (tid < w) red[tid] += red[tid + w];
        __syncthreads();
    }
    if (tid == 0) out[0] = red[0] * (1.0f / (float)(Bc * Nc));
}

extern "C" void kernel_launch(void* const* d_in, const int* in_sizes, int n_in,
                              void* d_out, int out_size)
{
    const float* x1 = (const float*)d_in[0];
    const float* x2 = (const float*)d_in[1];
    float* out = (float*)d_out;
    float* dist1 = out + 1;
    float* dist2 = out + 1 + Bc * Nc;

    zero_kernel<<<1, 512>>>();
    hist_kernel<<<256, 512>>>(x1, x2);
    prefix_kernel<<<1, 512>>>();
    scatter_kernel<<<256, 512>>>(x1, x2);
    nn_kernel<<<NN_GRID, NN_THREADS>>>(dist1, dist2);

    sum_stage1<<<128, 256>>>(out + 1);
    sum_stage2<<<1, 128>>>(out);
}